// round 13
// baseline (speedup 1.0000x reference)
#include <cuda_runtime.h>
#include <cuda_fp16.h>
#include <math.h>

#define S_LEN 2048
#define DIM 4096
#define NH 32
#define NKV 8
#define HD 128
#define KV_DIM 1024

// f16 scratch (allocation-free rule: __device__ globals)
__device__ __half g_xh[S_LEN * DIM];
__device__ __half g_wqh[DIM * DIM];
__device__ __half g_wkh[KV_DIM * DIM];
__device__ __half g_wvh[KV_DIM * DIM];
__device__ __half g_woh[DIM * DIM];
__device__ __half g_q[S_LEN * DIM];
__device__ __half g_k[S_LEN * KV_DIM];
__device__ __half g_v[S_LEN * KV_DIM];
__device__ __half g_attn[S_LEN * DIM];

// ---------------------------------------------------------------------------
// helpers
// ---------------------------------------------------------------------------
__device__ __forceinline__ unsigned smem_u32(const void* p) {
    unsigned a;
    asm("{ .reg .u64 t; cvta.to.shared.u64 t, %1; cvt.u32.u64 %0, t; }" : "=r"(a) : "l"(p));
    return a;
}

__device__ __forceinline__ void mma_f16(float c[4], const unsigned a[4], const unsigned b[2]) {
    asm volatile(
        "mma.sync.aligned.m16n8k16.row.col.f32.f16.f16.f32 "
        "{%0,%1,%2,%3},{%4,%5,%6,%7},{%8,%9},{%0,%1,%2,%3};"
        : "+f"(c[0]), "+f"(c[1]), "+f"(c[2]), "+f"(c[3])
        : "r"(a[0]), "r"(a[1]), "r"(a[2]), "r"(a[3]), "r"(b[0]), "r"(b[1]));
}

__device__ __forceinline__ void ldsm4(unsigned r[4], unsigned addr) {
    asm volatile("ldmatrix.sync.aligned.m8n8.x4.shared.b16 {%0,%1,%2,%3}, [%4];"
                 : "=r"(r[0]), "=r"(r[1]), "=r"(r[2]), "=r"(r[3]) : "r"(addr));
}

__device__ __forceinline__ void ldsm4t(unsigned r[4], unsigned addr) {
    asm volatile("ldmatrix.sync.aligned.m8n8.x4.trans.shared.b16 {%0,%1,%2,%3}, [%4];"
                 : "=r"(r[0]), "=r"(r[1]), "=r"(r[2]), "=r"(r[3]) : "r"(addr));
}

__device__ __forceinline__ void cpa16(unsigned dst, const void* src) {
    asm volatile("cp.async.cg.shared.global [%0], [%1], 16;" :: "r"(dst), "l"(src));
}

__device__ __forceinline__ unsigned packh2(float a, float b) {
    unsigned r;
    asm("cvt.rn.f16x2.f32 %0, %1, %2;" : "=r"(r) : "f"(b), "f"(a));
    return r;
}

// ---------------------------------------------------------------------------
// single merged fp32 -> fp16 conversion, 16 elems/thread (4 indep float4)
// ---------------------------------------------------------------------------
#define SEG_X  8388608ull
#define SEG_WQ 25165824ull
#define SEG_WK 29360128ull
#define SEG_WV 33554432ull
#define SEG_WO 50331648ull

__global__ void cvt_all(const float* __restrict__ x,  const float* __restrict__ wq,
                        const float* __restrict__ wk, const float* __restrict__ wv,
                        const float* __restrict__ wo,
                        __half* xh, __half* wqh, __half* wkh, __half* wvh, __half* woh) {
    size_t i = ((size_t)blockIdx.x * 256 + threadIdx.x) * 16;
    if (i >= SEG_WO) return;
    const float* s; __half* d; size_t off;
    if (i < SEG_X)       { s = x;  d = xh;  off = i; }
    else if (i < SEG_WQ) { s = wq; d = wqh; off = i - SEG_X; }
    else if (i < SEG_WK) { s = wk; d = wkh; off = i - SEG_WQ; }
    else if (i < SEG_WV) { s = wv; d = wvh; off = i - SEG_WK; }
    else                 { s = wo; d = woh; off = i - SEG_WV; }
    float4 v0 = ((const float4*)(s + off))[0];
    float4 v1 = ((const float4*)(s + off))[1];
    float4 v2 = ((const float4*)(s + off))[2];
    float4 v3 = ((const float4*)(s + off))[3];
    __half2* dp = (__half2*)(d + off);
    dp[0] = __floats2half2_rn(v0.x, v0.y);
    dp[1] = __floats2half2_rn(v0.z, v0.w);
    dp[2] = __floats2half2_rn(v1.x, v1.y);
    dp[3] = __floats2half2_rn(v1.z, v1.w);
    dp[4] = __floats2half2_rn(v2.x, v2.y);
    dp[5] = __floats2half2_rn(v2.z, v2.w);
    dp[6] = __floats2half2_rn(v3.x, v3.y);
    dp[7] = __floats2half2_rn(v3.z, v3.w);
}

// ---------------------------------------------------------------------------
// fp16 GEMM (R10/R12 config): CTA 128x256, K-step 64, 4-stage cp.async,
// register double-buffered fragments, f32 accumulate.
// ---------------------------------------------------------------------------
#define AST 72
#define A_H (128 * AST)
#define B_H (256 * AST)
#define STAGE_BYTES ((A_H + B_H) * 2)       // 55296
#define GSMEM (4 * STAGE_BYTES)             // 221184

__device__ __forceinline__ void g_load_stage(unsigned sbuf, const __half* Ap,
                                             const __half* Bp, int kt, int K, int tid) {
#pragma unroll
    for (int t = 0; t < 4; t++) {
        int idx = tid + t * 256;
        int row = idx >> 3, ch = idx & 7;
        cpa16(sbuf + (row * AST + ch * 8) * 2, Ap + (size_t)row * K + kt + ch * 8);
    }
#pragma unroll
    for (int t = 0; t < 8; t++) {
        int idx = tid + t * 256;
        int row = idx >> 3, ch = idx & 7;
        cpa16(sbuf + (A_H + row * AST + ch * 8) * 2, Bp + (size_t)row * K + kt + ch * 8);
    }
}

__global__ __launch_bounds__(256, 1)
void gemm_f16(const __half* __restrict__ Ah,
              const __half* __restrict__ B0, const __half* __restrict__ B1,
              const __half* __restrict__ B2,
              void* C0, void* C1, void* C2,
              int ldc0, int ldc1, int ldc2,
              int n1, int n2, int K, int out_f32) {
    extern __shared__ __align__(16) char smem[];
    const unsigned sbase = smem_u32(smem);
    const int tid = threadIdx.x, lane = tid & 31, warp = tid >> 5;
    const int mbase = (warp >> 2) * 64, nbase = (warp & 3) * 64;
    const int m0 = blockIdx.y * 128;
    const int nt = blockIdx.x;

    const __half* Bsel; void* Csel; int ldc, ncol0;
    if (nt < n1)      { Bsel = B0 + (size_t)nt * 256 * K;        Csel = C0; ldc = ldc0; ncol0 = nt * 256; }
    else if (nt < n2) { Bsel = B1 + (size_t)(nt - n1) * 256 * K; Csel = C1; ldc = ldc1; ncol0 = (nt - n1) * 256; }
    else              { Bsel = B2 + (size_t)(nt - n2) * 256 * K; Csel = C2; ldc = ldc2; ncol0 = (nt - n2) * 256; }
    const __half* Ap = Ah + (size_t)m0 * K;

    float acc[4][8][4];
#pragma unroll
    for (int i = 0; i < 4; i++)
#pragma unroll
        for (int j = 0; j < 8; j++)
#pragma unroll
            for (int r = 0; r < 4; r++) acc[i][j][r] = 0.f;

    const int NS = K / 64;
    g_load_stage(sbase, Ap, Bsel, 0, K, tid);
    asm volatile("cp.async.commit_group;" ::: "memory");
    g_load_stage(sbase + STAGE_BYTES, Ap, Bsel, 64, K, tid);
    asm volatile("cp.async.commit_group;" ::: "memory");
    g_load_stage(sbase + 2 * STAGE_BYTES, Ap, Bsel, 128, K, tid);
    asm volatile("cp.async.commit_group;" ::: "memory");

    for (int s = 0; s < NS; s++) {
        if (s <= NS - 3)      asm volatile("cp.async.wait_group 2;" ::: "memory");
        else if (s == NS - 2) asm volatile("cp.async.wait_group 1;" ::: "memory");
        else                  asm volatile("cp.async.wait_group 0;" ::: "memory");
        __syncthreads();
        if (s + 3 < NS) {
            g_load_stage(sbase + ((s + 3) & 3) * STAGE_BYTES, Ap, Bsel, (s + 3) * 64, K, tid);
            asm volatile("cp.async.commit_group;" ::: "memory");
        }
        const unsigned sA = sbase + (s & 3) * STAGE_BYTES;
        const unsigned sB = sA + A_H * 2;

        unsigned afr[2][4][4], bfr[2][8][2];
#pragma unroll
        for (int mt = 0; mt < 4; mt++)
            ldsm4(afr[0][mt], sA + ((mbase + mt * 16 + (lane & 15)) * AST + (lane >> 4) * 8) * 2);
#pragma unroll
        for (int p = 0; p < 4; p++) {
            unsigned t4[4];
            ldsm4(t4, sB + ((nbase + p * 16 + (lane & 15)) * AST + (lane >> 4) * 8) * 2);
            bfr[0][2 * p][0] = t4[0]; bfr[0][2 * p][1] = t4[2];
            bfr[0][2 * p + 1][0] = t4[1]; bfr[0][2 * p + 1][1] = t4[3];
        }
#pragma unroll
        for (int kc = 0; kc < 4; kc++) {
            const int cur = kc & 1, nxt = cur ^ 1;
            if (kc < 3) {
                const int ko = (kc + 1) * 16;
#pragma unroll
                for (int mt = 0; mt < 4; mt++)
                    ldsm4(afr[nxt][mt], sA + ((mbase + mt * 16 + (lane & 15)) * AST + ko + (lane >> 4) * 8) * 2);
#pragma unroll
                for (int p = 0; p < 4; p++) {
                    unsigned t4[4];
                    ldsm4(t4, sB + ((nbase + p * 16 + (lane & 15)) * AST + ko + (lane >> 4) * 8) * 2);
                    bfr[nxt][2 * p][0] = t4[0]; bfr[nxt][2 * p][1] = t4[2];
                    bfr[nxt][2 * p + 1][0] = t4[1]; bfr[nxt][2 * p + 1][1] = t4[3];
                }
            }
#pragma unroll
            for (int mt = 0; mt < 4; mt++)
#pragma unroll
                for (int n8 = 0; n8 < 8; n8++)
                    mma_f16(acc[mt][n8], afr[cur][mt], bfr[cur][n8]);
        }
    }

#pragma unroll
    for (int mt = 0; mt < 4; mt++) {
        int row0 = m0 + mbase + mt * 16 + (lane >> 2);
#pragma unroll
        for (int n8 = 0; n8 < 8; n8++) {
            int col = ncol0 + nbase + n8 * 8 + 2 * (lane & 3);
            if (out_f32) {
                float* Cp = (float*)Csel;
                *(float2*)(Cp + (size_t)row0 * ldc + col)       = make_float2(acc[mt][n8][0], acc[mt][n8][1]);
                *(float2*)(Cp + (size_t)(row0 + 8) * ldc + col) = make_float2(acc[mt][n8][2], acc[mt][n8][3]);
            } else {
                __half* Cp = (__half*)Csel;
                *(__half2*)(Cp + (size_t)row0 * ldc + col)       = __floats2half2_rn(acc[mt][n8][0], acc[mt][n8][1]);
                *(__half2*)(Cp + (size_t)(row0 + 8) * ldc + col) = __floats2half2_rn(acc[mt][n8][2], acc[mt][n8][3]);
            }
        }
    }
}

// ---------------------------------------------------------------------------
// Warp-per-head-row RMSNorm + RoPE. Q heads additionally pre-scaled by
// 1/sqrt(HD) so flash can skip the score scaling.
// ---------------------------------------------------------------------------
__global__ __launch_bounds__(256)
void rmsnorm_rope_warp(__half* __restrict__ qb, __half* __restrict__ kb,
                       const float* __restrict__ qw_, const float* __restrict__ kw_,
                       const float* __restrict__ cosp, const float* __restrict__ sinp) {
    const int lane = threadIdx.x & 31;
    const int gw = blockIdx.x * 8 + (threadIdx.x >> 5);   // global warp = row id
    const int hh = gw / S_LEN;
    const int s  = gw - hh * S_LEN;
    __half* p;
    const float* w;
    float outsc;
    if (hh < NH) { p = qb + (size_t)s * DIM + hh * HD; w = qw_; outsc = 0.08838834764831845f; }
    else         { p = kb + (size_t)s * KV_DIM + (hh - NH) * HD; w = kw_; outsc = 1.f; }
    const int d0 = lane * 4;

    uint2 raw = *(const uint2*)(p + d0);
    __half2 h01 = *(__half2*)&raw.x;
    __half2 h23 = *(__half2*)&raw.y;
    float v[4];
    { float2 f0 = __half22float2(h01), f1 = __half22float2(h23);
      v[0] = f0.x; v[1] = f0.y; v[2] = f1.x; v[3] = f1.y; }

    float sq = v[0]*v[0] + v[1]*v[1] + v[2]*v[2] + v[3]*v[3];
#pragma unroll
    for (int off = 16; off > 0; off >>= 1)
        sq += __shfl_xor_sync(0xffffffffu, sq, off);
    const float r = rsqrtf(sq * (1.0f / HD) + 1e-6f);

    float4 wv4 = *(const float4*)(w + d0);
    float xn[4] = { v[0]*r*wv4.x, v[1]*r*wv4.y, v[2]*r*wv4.z, v[3]*r*wv4.w };

    const float sgn = (lane < 16) ? -1.f : 1.f;
    float rot[4];
#pragma unroll
    for (int j = 0; j < 4; j++)
        rot[j] = sgn * __shfl_xor_sync(0xffffffffu, xn[j], 16);

    const float* cp = cosp + (size_t)s * HD + d0;
    const float* sp = sinp + (size_t)s * HD + d0;
    float4 c4 = *(const float4*)cp;
    float4 s4 = *(const float4*)sp;
    __half2 o01 = __floats2half2_rn((xn[0]*c4.x + rot[0]*s4.x) * outsc,
                                    (xn[1]*c4.y + rot[1]*s4.y) * outsc);
    __half2 o23 = __floats2half2_rn((xn[2]*c4.z + rot[2]*s4.z) * outsc,
                                    (xn[3]*c4.w + rot[3]*s4.w) * outsc);
    uint2 outp;
    outp.x = *(unsigned*)&o01;
    outp.y = *(unsigned*)&o23;
    *(uint2*)(p + d0) = outp;
}

// ---------------------------------------------------------------------------
// Flash attention, fp16 mma. Q pre-scaled by 1/sqrt(HD) -> no score scaling.
// ---------------------------------------------------------------------------
#define FQS 136
#define TILE_H (128 * FQS)
#define FLASH_SMEM (5 * TILE_H * 2)

__device__ __forceinline__ void fa_load_kv(unsigned dstK, unsigned dstV,
                                           const __half* Kp, const __half* Vp,
                                           int n0, int kvh, int tid) {
#pragma unroll
    for (int t = 0; t < 8; t++) {
        int idx = tid + t * 256;
        int row = idx >> 4, ch = idx & 15;
        size_t g = (size_t)(n0 + row) * KV_DIM + kvh * HD + ch * 8;
        cpa16(dstK + (row * FQS + ch * 8) * 2, Kp + g);
        cpa16(dstV + (row * FQS + ch * 8) * 2, Vp + g);
    }
}

__global__ __launch_bounds__(256, 1)
void flash_f16(const __half* __restrict__ Q, const __half* __restrict__ K,
               const __half* __restrict__ V, __half* __restrict__ O) {
    extern __shared__ __align__(16) char fsm[];
    const unsigned uQ = smem_u32(fsm);
    const unsigned uK0 = uQ + TILE_H * 2;
    const unsigned uK1 = uK0 + TILE_H * 2;
    const unsigned uV0 = uK1 + TILE_H * 2;
    const unsigned uV1 = uV0 + TILE_H * 2;

    const int tid = threadIdx.x, lane = tid & 31, warp = tid >> 5;
    const int mtb = (gridDim.x - 1) - blockIdx.x;
    const int h = blockIdx.y;
    const int kvh = h >> 2;
    const int m0 = mtb * 128;
    const int NT = mtb + 1;

#pragma unroll
    for (int t = 0; t < 8; t++) {
        int idx = tid + t * 256;
        int row = idx >> 4, ch = idx & 15;
        cpa16(uQ + (row * FQS + ch * 8) * 2,
              Q + (size_t)(m0 + row) * DIM + h * HD + ch * 8);
    }
    fa_load_kv(uK0, uV0, K, V, 0, kvh, tid);
    asm volatile("cp.async.commit_group;" ::: "memory");

    float o[16][4];
    float mi[2] = {-1e30f, -1e30f}, li[2] = {0.f, 0.f};
#pragma unroll
    for (int i = 0; i < 16; i++)
#pragma unroll
        for (int j = 0; j < 4; j++) o[i][j] = 0.f;

    unsigned qf[8][4];

    const int lr = warp * 16 + (lane >> 2);
    const int gr0 = m0 + lr, gr1 = gr0 + 8;

    for (int nt = 0; nt < NT; nt++) {
        const int n0 = nt * 128;
        const unsigned uK = (nt & 1) ? uK1 : uK0;
        const unsigned uV = (nt & 1) ? uV1 : uV0;

        asm volatile("cp.async.wait_group 0;" ::: "memory");
        __syncthreads();

        if (nt == 0) {
#pragma unroll
            for (int kc = 0; kc < 8; kc++)
                ldsm4(qf[kc], uQ + ((warp * 16 + (lane & 15)) * FQS + kc * 16 + (lane >> 4) * 8) * 2);
        }
        if (nt + 1 < NT) {
            fa_load_kv((nt & 1) ? uK0 : uK1, (nt & 1) ? uV0 : uV1,
                       K, V, (nt + 1) * 128, kvh, tid);
            asm volatile("cp.async.commit_group;" ::: "memory");
        }

        float s[16][4];
#pragma unroll
        for (int i = 0; i < 16; i++)
#pragma unroll
            for (int j = 0; j < 4; j++) s[i][j] = 0.f;

#pragma unroll
        for (int kc = 0; kc < 8; kc++) {
#pragma unroll
            for (int p = 0; p < 8; p++) {
                unsigned t4[4];
                ldsm4(t4, uK + ((p * 16 + (lane & 15)) * FQS + kc * 16 + (lane >> 4) * 8) * 2);
                unsigned b0[2] = {t4[0], t4[2]};
                unsigned b1[2] = {t4[1], t4[3]};
                mma_f16(s[2 * p], qf[kc], b0);
                mma_f16(s[2 * p + 1], qf[kc], b1);
            }
        }

        // causal mask only (scores already scaled via pre-scaled Q)
        if (nt == NT - 1) {
#pragma unroll
            for (int n8 = 0; n8 < 16; n8++) {
                int gc = n0 + n8 * 8 + 2 * (lane & 3);
                if (gc     > gr0) s[n8][0] = -1e30f;
                if (gc + 1 > gr0) s[n8][1] = -1e30f;
                if (gc     > gr1) s[n8][2] = -1e30f;
                if (gc + 1 > gr1) s[n8][3] = -1e30f;
            }
        }

#pragma unroll
        for (int rr = 0; rr < 2; rr++) {
            float mloc = -1e30f;
#pragma unroll
            for (int n8 = 0; n8 < 16; n8++)
                mloc = fmaxf(mloc, fmaxf(s[n8][2 * rr], s[n8][2 * rr + 1]));
            mloc = fmaxf(mloc, __shfl_xor_sync(0xffffffffu, mloc, 1));
            mloc = fmaxf(mloc, __shfl_xor_sync(0xffffffffu, mloc, 2));
            float mnew = fmaxf(mi[rr], mloc);
            float corr = __expf(mi[rr] - mnew);
            float rs = 0.f;
#pragma unroll
            for (int n8 = 0; n8 < 16; n8++) {
                float p0 = __expf(s[n8][2 * rr] - mnew);
                float p1 = __expf(s[n8][2 * rr + 1] - mnew);
                s[n8][2 * rr] = p0; s[n8][2 * rr + 1] = p1;
                rs += p0 + p1;
            }
            rs += __shfl_xor_sync(0xffffffffu, rs, 1);
            rs += __shfl_xor_sync(0xffffffffu, rs, 2);
            li[rr] = li[rr] * corr + rs;
            mi[rr] = mnew;
#pragma unroll
            for (int i = 0; i < 16; i++) {
                o[i][2 * rr]     *= corr;
                o[i][2 * rr + 1] *= corr;
            }
        }

#pragma unroll
        for (int kc = 0; kc < 8; kc++) {
            unsigned a[4];
            a[0] = packh2(s[2 * kc][0],     s[2 * kc][1]);
            a[1] = packh2(s[2 * kc][2],     s[2 * kc][3]);
            a[2] = packh2(s[2 * kc + 1][0], s[2 * kc + 1][1]);
            a[3] = packh2(s[2 * kc + 1][2], s[2 * kc + 1][3]);
#pragma unroll
            for (int p = 0; p < 8; p++) {
                unsigned t4[4];
                ldsm4t(t4, uV + ((kc * 16 + ((lane >> 3) & 1) * 8 + (lane & 7)) * FQS
                                 + p * 16 + (lane >> 4) * 8) * 2);
                unsigned b0[2] = {t4[0], t4[1]};
                unsigned b1[2] = {t4[2], t4[3]};
                mma_f16(o[2 * p], a, b0);
                mma_f16(o[2 * p + 1], a, b1);
            }
        }
    }

    float inv0 = 1.f / li[0], inv1 = 1.f / li[1];
    const int row0 = m0 + warp * 16 + (lane >> 2);
#pragma unroll
    for (int n16 = 0; n16 < 16; n16++) {
        int gc = n16 * 8 + 2 * (lane & 3);
        *(__half2*)(O + (size_t)row0 * DIM + h * HD + gc) =
            __floats2half2_rn(o[n16][0] * inv0, o[n16][1] * inv0);
        *(__half2*)(O + (size_t)(row0 + 8) * DIM + h * HD + gc) =
            __floats2half2_rn(o[n16][2] * inv1, o[n16][3] * inv1);
    }
}

// ---------------------------------------------------------------------------
extern "C" void kernel_launch(void* const* d_in, const int* in_sizes, int n_in,
                              void* d_out, int out_size) {
    const float* x    = (const float*)d_in[0];
    const float* cosp = (const float*)d_in[1];
    const float* sinp = (const float*)d_in[2];
    const float* wq   = (const float*)d_in[3];
    const float* wk   = (const float*)d_in[4];
    const float* wv   = (const float*)d_in[5];
    const float* wo   = (const float*)d_in[6];
    const float* qw   = (const float*)d_in[7];
    const float* kw   = (const float*)d_in[8];
    float* out = (float*)d_out;

    __half *xh, *wqh, *wkh, *wvh, *woh, *q, *k, *v, *attn;
    cudaGetSymbolAddress((void**)&xh, g_xh);
    cudaGetSymbolAddress((void**)&wqh, g_wqh);
    cudaGetSymbolAddress((void**)&wkh, g_wkh);
    cudaGetSymbolAddress((void**)&wvh, g_wvh);
    cudaGetSymbolAddress((void**)&woh, g_woh);
    cudaGetSymbolAddress((void**)&q, g_q);
    cudaGetSymbolAddress((void**)&k, g_k);
    cudaGetSymbolAddress((void**)&v, g_v);
    cudaGetSymbolAddress((void**)&attn, g_attn);

    cudaFuncSetAttribute(gemm_f16, cudaFuncAttributeMaxDynamicSharedMemorySize, GSMEM);
    cudaFuncSetAttribute(flash_f16, cudaFuncAttributeMaxDynamicSharedMemorySize, FLASH_SMEM);

    // one merged fp32 -> fp16 conversion (16 elems/thread)
    cvt_all<<<(unsigned)((SEG_WO / 16 + 255) / 256), 256>>>(
        x, wq, wk, wv, wo, xh, wqh, wkh, wvh, woh);

    // fused QKV projection: 24 N-tiles of 256 (16 Q | 4 K | 4 V), f16 out
    gemm_f16<<<dim3(24, S_LEN / 128), 256, GSMEM>>>(
        xh, wqh, wkh, wvh, q, k, v, DIM, KV_DIM, KV_DIM, 16, 20, DIM, 0);

    // warp-per-row rmsnorm+rope (q pre-scaled by 1/sqrt(HD))
    rmsnorm_rope_warp<<<S_LEN * (NH + NKV) / 8, 256>>>(q, k, qw, kw, cosp, sinp);

    flash_f16<<<dim3(S_LEN / 128, NH), 256, FLASH_SMEM>>>(q, k, v, attn);

    // output projection: 16 N-tiles of 256, f32 out
    gemm_f16<<<dim3(16, S_LEN / 128), 256, GSMEM>>>(
        attn, woh, woh, woh, out, out, out, DIM, DIM, DIM, 16, 20, DIM, 1);
}

// round 14
// speedup vs baseline: 1.0733x; 1.0733x over previous
#include <cuda_runtime.h>
#include <cuda_fp16.h>
#include <math.h>

#define S_LEN 2048
#define DIM 4096
#define NH 32
#define NKV 8
#define HD 128
#define KV_DIM 1024

// f16 scratch (allocation-free rule: __device__ globals)
__device__ __half g_xh[S_LEN * DIM];
__device__ __half g_wqh[DIM * DIM];
__device__ __half g_wkh[KV_DIM * DIM];
__device__ __half g_wvh[KV_DIM * DIM];
__device__ __half g_woh[DIM * DIM];
__device__ __half g_q[S_LEN * DIM];
__device__ __half g_k[S_LEN * KV_DIM];
__device__ __half g_v[S_LEN * KV_DIM];
__device__ __half g_attn[S_LEN * DIM];

// ---------------------------------------------------------------------------
// helpers
// ---------------------------------------------------------------------------
__device__ __forceinline__ unsigned smem_u32(const void* p) {
    unsigned a;
    asm("{ .reg .u64 t; cvta.to.shared.u64 t, %1; cvt.u32.u64 %0, t; }" : "=r"(a) : "l"(p));
    return a;
}

__device__ __forceinline__ void mma_f16(float c[4], const unsigned a[4], const unsigned b[2]) {
    asm volatile(
        "mma.sync.aligned.m16n8k16.row.col.f32.f16.f16.f32 "
        "{%0,%1,%2,%3},{%4,%5,%6,%7},{%8,%9},{%0,%1,%2,%3};"
        : "+f"(c[0]), "+f"(c[1]), "+f"(c[2]), "+f"(c[3])
        : "r"(a[0]), "r"(a[1]), "r"(a[2]), "r"(a[3]), "r"(b[0]), "r"(b[1]));
}

__device__ __forceinline__ void ldsm4(unsigned r[4], unsigned addr) {
    asm volatile("ldmatrix.sync.aligned.m8n8.x4.shared.b16 {%0,%1,%2,%3}, [%4];"
                 : "=r"(r[0]), "=r"(r[1]), "=r"(r[2]), "=r"(r[3]) : "r"(addr));
}

__device__ __forceinline__ void ldsm4t(unsigned r[4], unsigned addr) {
    asm volatile("ldmatrix.sync.aligned.m8n8.x4.trans.shared.b16 {%0,%1,%2,%3}, [%4];"
                 : "=r"(r[0]), "=r"(r[1]), "=r"(r[2]), "=r"(r[3]) : "r"(addr));
}

__device__ __forceinline__ void cpa16(unsigned dst, const void* src) {
    asm volatile("cp.async.cg.shared.global [%0], [%1], 16;" :: "r"(dst), "l"(src));
}

__device__ __forceinline__ unsigned packh2(float a, float b) {
    unsigned r;
    asm("cvt.rn.f16x2.f32 %0, %1, %2;" : "=r"(r) : "f"(b), "f"(a));
    return r;
}

// ---------------------------------------------------------------------------
// single merged fp32 -> fp16 conversion, 8 elems/thread (R12 measured-best)
// ---------------------------------------------------------------------------
#define SEG_X  8388608ull
#define SEG_WQ 25165824ull
#define SEG_WK 29360128ull
#define SEG_WV 33554432ull
#define SEG_WO 50331648ull

__global__ void cvt_all(const float* __restrict__ x,  const float* __restrict__ wq,
                        const float* __restrict__ wk, const float* __restrict__ wv,
                        const float* __restrict__ wo,
                        __half* xh, __half* wqh, __half* wkh, __half* wvh, __half* woh) {
    size_t i = ((size_t)blockIdx.x * 256 + threadIdx.x) * 8;
    if (i >= SEG_WO) return;
    const float* s; __half* d; size_t off;
    if (i < SEG_X)       { s = x;  d = xh;  off = i; }
    else if (i < SEG_WQ) { s = wq; d = wqh; off = i - SEG_X; }
    else if (i < SEG_WK) { s = wk; d = wkh; off = i - SEG_WQ; }
    else if (i < SEG_WV) { s = wv; d = wvh; off = i - SEG_WK; }
    else                 { s = wo; d = woh; off = i - SEG_WV; }
    float4 v0 = ((const float4*)(s + off))[0];
    float4 v1 = ((const float4*)(s + off))[1];
    __half2* dp = (__half2*)(d + off);
    dp[0] = __floats2half2_rn(v0.x, v0.y);
    dp[1] = __floats2half2_rn(v0.z, v0.w);
    dp[2] = __floats2half2_rn(v1.x, v1.y);
    dp[3] = __floats2half2_rn(v1.z, v1.w);
}

// ---------------------------------------------------------------------------
// fp16 GEMM (R10/R12 config): CTA 128x256, K-step 64, 4-stage cp.async,
// register double-buffered fragments, f32 accumulate.
// ---------------------------------------------------------------------------
#define AST 72
#define A_H (128 * AST)
#define B_H (256 * AST)
#define STAGE_BYTES ((A_H + B_H) * 2)       // 55296
#define GSMEM (4 * STAGE_BYTES)             // 221184

__device__ __forceinline__ void g_load_stage(unsigned sbuf, const __half* Ap,
                                             const __half* Bp, int kt, int K, int tid) {
#pragma unroll
    for (int t = 0; t < 4; t++) {
        int idx = tid + t * 256;
        int row = idx >> 3, ch = idx & 7;
        cpa16(sbuf + (row * AST + ch * 8) * 2, Ap + (size_t)row * K + kt + ch * 8);
    }
#pragma unroll
    for (int t = 0; t < 8; t++) {
        int idx = tid + t * 256;
        int row = idx >> 3, ch = idx & 7;
        cpa16(sbuf + (A_H + row * AST + ch * 8) * 2, Bp + (size_t)row * K + kt + ch * 8);
    }
}

__global__ __launch_bounds__(256, 1)
void gemm_f16(const __half* __restrict__ Ah,
              const __half* __restrict__ B0, const __half* __restrict__ B1,
              const __half* __restrict__ B2,
              void* C0, void* C1, void* C2,
              int ldc0, int ldc1, int ldc2,
              int n1, int n2, int K, int out_f32) {
    extern __shared__ __align__(16) char smem[];
    const unsigned sbase = smem_u32(smem);
    const int tid = threadIdx.x, lane = tid & 31, warp = tid >> 5;
    const int mbase = (warp >> 2) * 64, nbase = (warp & 3) * 64;
    const int m0 = blockIdx.y * 128;
    const int nt = blockIdx.x;

    const __half* Bsel; void* Csel; int ldc, ncol0;
    if (nt < n1)      { Bsel = B0 + (size_t)nt * 256 * K;        Csel = C0; ldc = ldc0; ncol0 = nt * 256; }
    else if (nt < n2) { Bsel = B1 + (size_t)(nt - n1) * 256 * K; Csel = C1; ldc = ldc1; ncol0 = (nt - n1) * 256; }
    else              { Bsel = B2 + (size_t)(nt - n2) * 256 * K; Csel = C2; ldc = ldc2; ncol0 = (nt - n2) * 256; }
    const __half* Ap = Ah + (size_t)m0 * K;

    float acc[4][8][4];
#pragma unroll
    for (int i = 0; i < 4; i++)
#pragma unroll
        for (int j = 0; j < 8; j++)
#pragma unroll
            for (int r = 0; r < 4; r++) acc[i][j][r] = 0.f;

    const int NS = K / 64;
    g_load_stage(sbase, Ap, Bsel, 0, K, tid);
    asm volatile("cp.async.commit_group;" ::: "memory");
    g_load_stage(sbase + STAGE_BYTES, Ap, Bsel, 64, K, tid);
    asm volatile("cp.async.commit_group;" ::: "memory");
    g_load_stage(sbase + 2 * STAGE_BYTES, Ap, Bsel, 128, K, tid);
    asm volatile("cp.async.commit_group;" ::: "memory");

    for (int s = 0; s < NS; s++) {
        if (s <= NS - 3)      asm volatile("cp.async.wait_group 2;" ::: "memory");
        else if (s == NS - 2) asm volatile("cp.async.wait_group 1;" ::: "memory");
        else                  asm volatile("cp.async.wait_group 0;" ::: "memory");
        __syncthreads();
        if (s + 3 < NS) {
            g_load_stage(sbase + ((s + 3) & 3) * STAGE_BYTES, Ap, Bsel, (s + 3) * 64, K, tid);
            asm volatile("cp.async.commit_group;" ::: "memory");
        }
        const unsigned sA = sbase + (s & 3) * STAGE_BYTES;
        const unsigned sB = sA + A_H * 2;

        unsigned afr[2][4][4], bfr[2][8][2];
#pragma unroll
        for (int mt = 0; mt < 4; mt++)
            ldsm4(afr[0][mt], sA + ((mbase + mt * 16 + (lane & 15)) * AST + (lane >> 4) * 8) * 2);
#pragma unroll
        for (int p = 0; p < 4; p++) {
            unsigned t4[4];
            ldsm4(t4, sB + ((nbase + p * 16 + (lane & 15)) * AST + (lane >> 4) * 8) * 2);
            bfr[0][2 * p][0] = t4[0]; bfr[0][2 * p][1] = t4[2];
            bfr[0][2 * p + 1][0] = t4[1]; bfr[0][2 * p + 1][1] = t4[3];
        }
#pragma unroll
        for (int kc = 0; kc < 4; kc++) {
            const int cur = kc & 1, nxt = cur ^ 1;
            if (kc < 3) {
                const int ko = (kc + 1) * 16;
#pragma unroll
                for (int mt = 0; mt < 4; mt++)
                    ldsm4(afr[nxt][mt], sA + ((mbase + mt * 16 + (lane & 15)) * AST + ko + (lane >> 4) * 8) * 2);
#pragma unroll
                for (int p = 0; p < 4; p++) {
                    unsigned t4[4];
                    ldsm4(t4, sB + ((nbase + p * 16 + (lane & 15)) * AST + ko + (lane >> 4) * 8) * 2);
                    bfr[nxt][2 * p][0] = t4[0]; bfr[nxt][2 * p][1] = t4[2];
                    bfr[nxt][2 * p + 1][0] = t4[1]; bfr[nxt][2 * p + 1][1] = t4[3];
                }
            }
#pragma unroll
            for (int mt = 0; mt < 4; mt++)
#pragma unroll
                for (int n8 = 0; n8 < 8; n8++)
                    mma_f16(acc[mt][n8], afr[cur][mt], bfr[cur][n8]);
        }
    }

#pragma unroll
    for (int mt = 0; mt < 4; mt++) {
        int row0 = m0 + mbase + mt * 16 + (lane >> 2);
#pragma unroll
        for (int n8 = 0; n8 < 8; n8++) {
            int col = ncol0 + nbase + n8 * 8 + 2 * (lane & 3);
            if (out_f32) {
                float* Cp = (float*)Csel;
                *(float2*)(Cp + (size_t)row0 * ldc + col)       = make_float2(acc[mt][n8][0], acc[mt][n8][1]);
                *(float2*)(Cp + (size_t)(row0 + 8) * ldc + col) = make_float2(acc[mt][n8][2], acc[mt][n8][3]);
            } else {
                __half* Cp = (__half*)Csel;
                *(__half2*)(Cp + (size_t)row0 * ldc + col)       = __floats2half2_rn(acc[mt][n8][0], acc[mt][n8][1]);
                *(__half2*)(Cp + (size_t)(row0 + 8) * ldc + col) = __floats2half2_rn(acc[mt][n8][2], acc[mt][n8][3]);
            }
        }
    }
}

// ---------------------------------------------------------------------------
// Warp-per-head-row RMSNorm + RoPE, q pre-scaled by 1/sqrt(HD) (R13).
// ---------------------------------------------------------------------------
__global__ __launch_bounds__(256)
void rmsnorm_rope_warp(__half* __restrict__ qb, __half* __restrict__ kb,
                       const float* __restrict__ qw_, const float* __restrict__ kw_,
                       const float* __restrict__ cosp, const float* __restrict__ sinp) {
    const int lane = threadIdx.x & 31;
    const int gw = blockIdx.x * 8 + (threadIdx.x >> 5);
    const int hh = gw / S_LEN;
    const int s  = gw - hh * S_LEN;
    __half* p;
    const float* w;
    float outsc;
    if (hh < NH) { p = qb + (size_t)s * DIM + hh * HD; w = qw_; outsc = 0.08838834764831845f; }
    else         { p = kb + (size_t)s * KV_DIM + (hh - NH) * HD; w = kw_; outsc = 1.f; }
    const int d0 = lane * 4;

    uint2 raw = *(const uint2*)(p + d0);
    __half2 h01 = *(__half2*)&raw.x;
    __half2 h23 = *(__half2*)&raw.y;
    float v[4];
    { float2 f0 = __half22float2(h01), f1 = __half22float2(h23);
      v[0] = f0.x; v[1] = f0.y; v[2] = f1.x; v[3] = f1.y; }

    float sq = v[0]*v[0] + v[1]*v[1] + v[2]*v[2] + v[3]*v[3];
#pragma unroll
    for (int off = 16; off > 0; off >>= 1)
        sq += __shfl_xor_sync(0xffffffffu, sq, off);
    const float r = rsqrtf(sq * (1.0f / HD) + 1e-6f);

    float4 wv4 = *(const float4*)(w + d0);
    float xn[4] = { v[0]*r*wv4.x, v[1]*r*wv4.y, v[2]*r*wv4.z, v[3]*r*wv4.w };

    const float sgn = (lane < 16) ? -1.f : 1.f;
    float rot[4];
#pragma unroll
    for (int j = 0; j < 4; j++)
        rot[j] = sgn * __shfl_xor_sync(0xffffffffu, xn[j], 16);

    const float* cp = cosp + (size_t)s * HD + d0;
    const float* sp = sinp + (size_t)s * HD + d0;
    float4 c4 = *(const float4*)cp;
    float4 s4 = *(const float4*)sp;
    __half2 o01 = __floats2half2_rn((xn[0]*c4.x + rot[0]*s4.x) * outsc,
                                    (xn[1]*c4.y + rot[1]*s4.y) * outsc);
    __half2 o23 = __floats2half2_rn((xn[2]*c4.z + rot[2]*s4.z) * outsc,
                                    (xn[3]*c4.w + rot[3]*s4.w) * outsc);
    uint2 outp;
    outp.x = *(unsigned*)&o01;
    outp.y = *(unsigned*)&o23;
    *(uint2*)(p + d0) = outp;
}

// ---------------------------------------------------------------------------
// Flash attention, fp16 mma, Q pre-scaled (R13 version; 155 us measured).
// ---------------------------------------------------------------------------
#define FQS 136
#define TILE_H (128 * FQS)
#define FLASH_SMEM (5 * TILE_H * 2)

__device__ __forceinline__ void fa_load_kv(unsigned dstK, unsigned dstV,
                                           const __half* Kp, const __half* Vp,
                                           int n0, int kvh, int tid) {
#pragma unroll
    for (int t = 0; t < 8; t++) {
        int idx = tid + t * 256;
        int row = idx >> 4, ch = idx & 15;
        size_t g = (size_t)(n0 + row) * KV_DIM + kvh * HD + ch * 8;
        cpa16(dstK + (row * FQS + ch * 8) * 2, Kp + g);
        cpa16(dstV + (row * FQS + ch * 8) * 2, Vp + g);
    }
}

__global__ __launch_bounds__(256, 1)
void flash_f16(const __half* __restrict__ Q, const __half* __restrict__ K,
               const __half* __restrict__ V, __half* __restrict__ O) {
    extern __shared__ __align__(16) char fsm[];
    const unsigned uQ = smem_u32(fsm);
    const unsigned uK0 = uQ + TILE_H * 2;
    const unsigned uK1 = uK0 + TILE_H * 2;
    const unsigned uV0 = uK1 + TILE_H * 2;
    const unsigned uV1 = uV0 + TILE_H * 2;

    const int tid = threadIdx.x, lane = tid & 31, warp = tid >> 5;
    const int mtb = (gridDim.x - 1) - blockIdx.x;
    const int h = blockIdx.y;
    const int kvh = h >> 2;
    const int m0 = mtb * 128;
    const int NT = mtb + 1;

#pragma unroll
    for (int t = 0; t < 8; t++) {
        int idx = tid + t * 256;
        int row = idx >> 4, ch = idx & 15;
        cpa16(uQ + (row * FQS + ch * 8) * 2,
              Q + (size_t)(m0 + row) * DIM + h * HD + ch * 8);
    }
    fa_load_kv(uK0, uV0, K, V, 0, kvh, tid);
    asm volatile("cp.async.commit_group;" ::: "memory");

    float o[16][4];
    float mi[2] = {-1e30f, -1e30f}, li[2] = {0.f, 0.f};
#pragma unroll
    for (int i = 0; i < 16; i++)
#pragma unroll
        for (int j = 0; j < 4; j++) o[i][j] = 0.f;

    unsigned qf[8][4];

    const int lr = warp * 16 + (lane >> 2);
    const int gr0 = m0 + lr, gr1 = gr0 + 8;

    for (int nt = 0; nt < NT; nt++) {
        const int n0 = nt * 128;
        const unsigned uK = (nt & 1) ? uK1 : uK0;
        const unsigned uV = (nt & 1) ? uV1 : uV0;

        asm volatile("cp.async.wait_group 0;" ::: "memory");
        __syncthreads();

        if (nt == 0) {
#pragma unroll
            for (int kc = 0; kc < 8; kc++)
                ldsm4(qf[kc], uQ + ((warp * 16 + (lane & 15)) * FQS + kc * 16 + (lane >> 4) * 8) * 2);
        }
        if (nt + 1 < NT) {
            fa_load_kv((nt & 1) ? uK0 : uK1, (nt & 1) ? uV0 : uV1,
                       K, V, (nt + 1) * 128, kvh, tid);
            asm volatile("cp.async.commit_group;" ::: "memory");
        }

        float s[16][4];
#pragma unroll
        for (int i = 0; i < 16; i++)
#pragma unroll
            for (int j = 0; j < 4; j++) s[i][j] = 0.f;

#pragma unroll
        for (int kc = 0; kc < 8; kc++) {
#pragma unroll
            for (int p = 0; p < 8; p++) {
                unsigned t4[4];
                ldsm4(t4, uK + ((p * 16 + (lane & 15)) * FQS + kc * 16 + (lane >> 4) * 8) * 2);
                unsigned b0[2] = {t4[0], t4[2]};
                unsigned b1[2] = {t4[1], t4[3]};
                mma_f16(s[2 * p], qf[kc], b0);
                mma_f16(s[2 * p + 1], qf[kc], b1);
            }
        }

        if (nt == NT - 1) {
#pragma unroll
            for (int n8 = 0; n8 < 16; n8++) {
                int gc = n0 + n8 * 8 + 2 * (lane & 3);
                if (gc     > gr0) s[n8][0] = -1e30f;
                if (gc + 1 > gr0) s[n8][1] = -1e30f;
                if (gc     > gr1) s[n8][2] = -1e30f;
                if (gc + 1 > gr1) s[n8][3] = -1e30f;
            }
        }

#pragma unroll
        for (int rr = 0; rr < 2; rr++) {
            float mloc = -1e30f;
#pragma unroll
            for (int n8 = 0; n8 < 16; n8++)
                mloc = fmaxf(mloc, fmaxf(s[n8][2 * rr], s[n8][2 * rr + 1]));
            mloc = fmaxf(mloc, __shfl_xor_sync(0xffffffffu, mloc, 1));
            mloc = fmaxf(mloc, __shfl_xor_sync(0xffffffffu, mloc, 2));
            float mnew = fmaxf(mi[rr], mloc);
            float corr = __expf(mi[rr] - mnew);
            float rs = 0.f;
#pragma unroll
            for (int n8 = 0; n8 < 16; n8++) {
                float p0 = __expf(s[n8][2 * rr] - mnew);
                float p1 = __expf(s[n8][2 * rr + 1] - mnew);
                s[n8][2 * rr] = p0; s[n8][2 * rr + 1] = p1;
                rs += p0 + p1;
            }
            rs += __shfl_xor_sync(0xffffffffu, rs, 1);
            rs += __shfl_xor_sync(0xffffffffu, rs, 2);
            li[rr] = li[rr] * corr + rs;
            mi[rr] = mnew;
#pragma unroll
            for (int i = 0; i < 16; i++) {
                o[i][2 * rr]     *= corr;
                o[i][2 * rr + 1] *= corr;
            }
        }

#pragma unroll
        for (int kc = 0; kc < 8; kc++) {
            unsigned a[4];
            a[0] = packh2(s[2 * kc][0],     s[2 * kc][1]);
            a[1] = packh2(s[2 * kc][2],     s[2 * kc][3]);
            a[2] = packh2(s[2 * kc + 1][0], s[2 * kc + 1][1]);
            a[3] = packh2(s[2 * kc + 1][2], s[2 * kc + 1][3]);
#pragma unroll
            for (int p = 0; p < 8; p++) {
                unsigned t4[4];
                ldsm4t(t4, uV + ((kc * 16 + ((lane >> 3) & 1) * 8 + (lane & 7)) * FQS
                                 + p * 16 + (lane >> 4) * 8) * 2);
                unsigned b0[2] = {t4[0], t4[1]};
                unsigned b1[2] = {t4[2], t4[3]};
                mma_f16(o[2 * p], a, b0);
                mma_f16(o[2 * p + 1], a, b1);
            }
        }
    }

    float inv0 = 1.f / li[0], inv1 = 1.f / li[1];
    const int row0 = m0 + warp * 16 + (lane >> 2);
#pragma unroll
    for (int n16 = 0; n16 < 16; n16++) {
        int gc = n16 * 8 + 2 * (lane & 3);
        *(__half2*)(O + (size_t)row0 * DIM + h * HD + gc) =
            __floats2half2_rn(o[n16][0] * inv0, o[n16][1] * inv0);
        *(__half2*)(O + (size_t)(row0 + 8) * DIM + h * HD + gc) =
            __floats2half2_rn(o[n16][2] * inv1, o[n16][3] * inv1);
    }
}

// ---------------------------------------------------------------------------
extern "C" void kernel_launch(void* const* d_in, const int* in_sizes, int n_in,
                              void* d_out, int out_size) {
    const float* x    = (const float*)d_in[0];
    const float* cosp = (const float*)d_in[1];
    const float* sinp = (const float*)d_in[2];
    const float* wq   = (const float*)d_in[3];
    const float* wk   = (const float*)d_in[4];
    const float* wv   = (const float*)d_in[5];
    const float* wo   = (const float*)d_in[6];
    const float* qw   = (const float*)d_in[7];
    const float* kw   = (const float*)d_in[8];
    float* out = (float*)d_out;

    __half *xh, *wqh, *wkh, *wvh, *woh, *q, *k, *v, *attn;
    cudaGetSymbolAddress((void**)&xh, g_xh);
    cudaGetSymbolAddress((void**)&wqh, g_wqh);
    cudaGetSymbolAddress((void**)&wkh, g_wkh);
    cudaGetSymbolAddress((void**)&wvh, g_wvh);
    cudaGetSymbolAddress((void**)&woh, g_woh);
    cudaGetSymbolAddress((void**)&q, g_q);
    cudaGetSymbolAddress((void**)&k, g_k);
    cudaGetSymbolAddress((void**)&v, g_v);
    cudaGetSymbolAddress((void**)&attn, g_attn);

    cudaFuncSetAttribute(gemm_f16, cudaFuncAttributeMaxDynamicSharedMemorySize, GSMEM);
    cudaFuncSetAttribute(flash_f16, cudaFuncAttributeMaxDynamicSharedMemorySize, FLASH_SMEM);

    // one merged fp32 -> fp16 conversion (8 elems/thread — measured best)
    cvt_all<<<(unsigned)((SEG_WO / 8 + 255) / 256), 256>>>(
        x, wq, wk, wv, wo, xh, wqh, wkh, wvh, woh);

    // fused QKV projection: 24 N-tiles of 256 (16 Q | 4 K | 4 V), f16 out
    gemm_f16<<<dim3(24, S_LEN / 128), 256, GSMEM>>>(
        xh, wqh, wkh, wvh, q, k, v, DIM, KV_DIM, KV_DIM, 16, 20, DIM, 0);

    // warp-per-row rmsnorm+rope (q pre-scaled by 1/sqrt(HD))
    rmsnorm_rope_warp<<<S_LEN * (NH + NKV) / 8, 256>>>(q, k, qw, kw, cosp, sinp);

    flash_f16<<<dim3(S_LEN / 128, NH), 256, FLASH_SMEM>>>(q, k, v, attn);

    // output projection: 16 N-tiles of 256, f32 out
    gemm_f16<<<dim3(16, S_LEN / 128), 256, GSMEM>>>(
        attn, woh, woh, woh, out, out, out, DIM, DIM, DIM, 16, 20, DIM, 1);
}